// round 13
// baseline (speedup 1.0000x reference)
#include <cuda_runtime.h>
#include <cuda_fp16.h>
#include <cstdint>

// ---------------- Problem constants ----------------
#define Bb     4
#define Ll     2048
#define Dm     1024
#define Ns     16
#define BL     (Bb * Ll)        // 8192 rows
#define LN_EPS 1e-5f

// ---------------- Scratch (device globals; no allocs allowed) ----------------
__device__ float  g_xproj[BL * 2 * Dm];   // [row][0:1024]=x_ssm, [1024:2048]=gate
__device__ float  g_xconv[BL * Dm];       // fp32 (scan, bc)
__device__ float  g_bc[BL * 2 * Ns];      // [row][0:16]=B, [16:32]=C
__device__ float  g_dt[BL * Dm];          // softplus'd
__device__ float  g_out[BL * Dm];         // after out proj, before LN
// fp16 operands for tensor-core GEMMs
__device__ __half g_xh[BL * Dm];
__device__ __half g_xconv_h[BL * Dm];
__device__ __half g_y_h[BL * Dm];
__device__ __half g_ipw_h[2 * Dm * Dm];
__device__ __half g_dtw_h[Dm * Dm];
__device__ __half g_ow_h[Dm * Dm];
// chunked-scan state: layout [b][chunk][d][n]
#define NCHUNK 8
#define CL (Ll / NCHUNK)          // 256
__device__ float g_hend  [Bb * NCHUNK * Dm * Ns];   // 2 MB
__device__ float g_ptot  [Bb * NCHUNK * Dm * Ns];   // 2 MB
__device__ float g_hstart[Bb * NCHUNK * Dm * Ns];   // 2 MB

__device__ __forceinline__ float softplus_f(float v) {
    return (v > 20.f) ? v : log1pf(__expf(v));
}

__device__ __forceinline__ uint32_t smem_u32(const void* p) {
    return (uint32_t)__cvta_generic_to_shared(p);
}
__device__ __forceinline__ void cp16(uint32_t dst, const void* src) {
    asm volatile("cp.async.cg.shared.global [%0], [%1], 16;\n" :: "r"(dst), "l"(src));
}
__device__ __forceinline__ void cp_commit() { asm volatile("cp.async.commit_group;\n"); }
template<int W> __device__ __forceinline__ void cp_wait() {
    asm volatile("cp.async.wait_group %0;\n" :: "n"(W));
}

// ================= f32 -> f16 conversion =================
__global__ void __launch_bounds__(256)
k_f2h(const float* __restrict__ src, __half* __restrict__ dst, int n4)
{
    int i = blockIdx.x * blockDim.x + threadIdx.x;
    if (i >= n4) return;
    float4 v = *(const float4*)(src + (size_t)i * 4);
    __half2 h0 = __floats2half2_rn(v.x, v.y);
    __half2 h1 = __floats2half2_rn(v.z, v.w);
    *(uint2*)(dst + (size_t)i * 4) = make_uint2(*(uint32_t*)&h0, *(uint32_t*)&h1);
}

// ================= fp16 tensor-core GEMM (proven 2-stage version) =================
#define GBM 128
#define GBN 128
#define GBK 32
#define LDAH 40   // halves per smem row (32 + 8 pad) -> conflict-free frag loads

__device__ __forceinline__ void mma_f16(float& c0, float& c1, float& c2, float& c3,
                                        uint32_t a0, uint32_t a1, uint32_t a2, uint32_t a3,
                                        uint32_t b0, uint32_t b1) {
    asm volatile(
        "mma.sync.aligned.m16n8k16.row.col.f32.f16.f16.f32 "
        "{%0,%1,%2,%3},{%4,%5,%6,%7},{%8,%9},{%0,%1,%2,%3};\n"
        : "+f"(c0), "+f"(c1), "+f"(c2), "+f"(c3)
        : "r"(a0), "r"(a1), "r"(a2), "r"(a3), "r"(b0), "r"(b1));
}

template<int ACT>
__device__ __forceinline__ void gemm_f16_body(const __half* __restrict__ A,
                                              const __half* __restrict__ Bw,
                                              const float* __restrict__ bias,
                                              float* __restrict__ C,
                                              int N, int K)
{
    __shared__ __align__(16) __half As[2][GBM][LDAH];
    __shared__ __align__(16) __half Bs[2][GBN][LDAH];

    const int tid  = threadIdx.x;
    const int lane = tid & 31;
    const int wid  = tid >> 5;
    const int g    = lane >> 2;      // 0..7
    const int tig  = lane & 3;       // 0..3
    const int warpM = wid >> 2;      // 0..1 -> m offset *64
    const int warpN = wid & 3;       // 0..3 -> n offset *32
    const int bm = blockIdx.y * GBM;
    const int bn = blockIdx.x * GBN;

    float c[4][4][4];
    #pragma unroll
    for (int mt = 0; mt < 4; mt++)
        #pragma unroll
        for (int nt = 0; nt < 4; nt++)
            #pragma unroll
            for (int r = 0; r < 4; r++) c[mt][nt][r] = 0.f;

    const int i0 = 2 * tid, i1 = 2 * tid + 1;
    const int r0c = i0 >> 2, o0 = (i0 & 3) * 8;
    const int r1c = i1 >> 2, o1 = (i1 & 3) * 8;
    const __half* Arow0 = A  + (size_t)(bm + r0c) * K + o0;
    const __half* Arow1 = A  + (size_t)(bm + r1c) * K + o1;
    const __half* Brow0 = Bw + (size_t)(bn + r0c) * K + o0;
    const __half* Brow1 = Bw + (size_t)(bn + r1c) * K + o1;
    uint32_t dA0 = smem_u32(&As[0][r0c][o0]);
    uint32_t dA1 = smem_u32(&As[0][r1c][o1]);
    uint32_t dB0 = smem_u32(&Bs[0][r0c][o0]);
    uint32_t dB1 = smem_u32(&Bs[0][r1c][o1]);
    const uint32_t bufStride = (uint32_t)(GBM * LDAH * 2);

    cp16(dA0, Arow0); cp16(dA1, Arow1);
    cp16(dB0, Brow0); cp16(dB1, Brow1);
    cp_commit();

    const int NK = K / GBK;
    for (int it = 0; it < NK; it++) {
        const int cur = it & 1;
        cp_wait<0>();
        __syncthreads();
        if (it + 1 < NK) {
            const int nxt = cur ^ 1;
            const int k0 = (it + 1) * GBK;
            cp16(dA0 + nxt * bufStride, Arow0 + k0);
            cp16(dA1 + nxt * bufStride, Arow1 + k0);
            cp16(dB0 + nxt * bufStride, Brow0 + k0);
            cp16(dB1 + nxt * bufStride, Brow1 + k0);
            cp_commit();
        }

        #pragma unroll
        for (int ks = 0; ks < 2; ks++) {
            const int kk = ks * 16;
            uint32_t a[4][4], bf[4][2];
            #pragma unroll
            for (int mt = 0; mt < 4; mt++) {
                const int m0 = warpM * 64 + mt * 16 + g;
                a[mt][0] = *(const uint32_t*)&As[cur][m0    ][kk + 2 * tig    ];
                a[mt][1] = *(const uint32_t*)&As[cur][m0 + 8][kk + 2 * tig    ];
                a[mt][2] = *(const uint32_t*)&As[cur][m0    ][kk + 2 * tig + 8];
                a[mt][3] = *(const uint32_t*)&As[cur][m0 + 8][kk + 2 * tig + 8];
            }
            #pragma unroll
            for (int nt = 0; nt < 4; nt++) {
                const int n0 = warpN * 32 + nt * 8 + g;
                bf[nt][0] = *(const uint32_t*)&Bs[cur][n0][kk + 2 * tig    ];
                bf[nt][1] = *(const uint32_t*)&Bs[cur][n0][kk + 2 * tig + 8];
            }
            #pragma unroll
            for (int mt = 0; mt < 4; mt++)
                #pragma unroll
                for (int nt = 0; nt < 4; nt++)
                    mma_f16(c[mt][nt][0], c[mt][nt][1], c[mt][nt][2], c[mt][nt][3],
                            a[mt][0], a[mt][1], a[mt][2], a[mt][3],
                            bf[nt][0], bf[nt][1]);
        }
    }

    #pragma unroll
    for (int mt = 0; mt < 4; mt++) {
        const int m = bm + warpM * 64 + mt * 16 + g;
        #pragma unroll
        for (int nt = 0; nt < 4; nt++) {
            const int n = bn + warpN * 32 + nt * 8 + tig * 2;
            const float b0v = bias[n], b1v = bias[n + 1];
            float v0 = c[mt][nt][0] + b0v;
            float v1 = c[mt][nt][1] + b1v;
            float v2 = c[mt][nt][2] + b0v;
            float v3 = c[mt][nt][3] + b1v;
            if (ACT == 1) { v0 = softplus_f(v0); v1 = softplus_f(v1); v2 = softplus_f(v2); v3 = softplus_f(v3); }
            *(float2*)&C[(size_t)m * N + n]       = make_float2(v0, v1);
            *(float2*)&C[(size_t)(m + 8) * N + n] = make_float2(v2, v3);
        }
    }
}

__global__ void __launch_bounds__(256)
k_gemm_inproj(const float* __restrict__ b)
{ gemm_f16_body<0>(g_xh, g_ipw_h, b, g_xproj, 2 * Dm, Dm); }

__global__ void __launch_bounds__(256)
k_gemm_dt(const float* __restrict__ b)
{ gemm_f16_body<1>(g_xconv_h, g_dtw_h, b, g_dt, Dm, Dm); }

__global__ void __launch_bounds__(256)
k_gemm_out(const float* __restrict__ b)
{ gemm_f16_body<0>(g_y_h, g_ow_h, b, g_out, Dm, Dm); }

// ================= thin BC projection: (8192,1024) @ (32,1024)^T =================
__global__ void __launch_bounds__(256)
k_bc(const float* __restrict__ w, const float* __restrict__ bias)
{
    const int row = blockIdx.x * 32 + (threadIdx.x >> 3);
    const int cg  = threadIdx.x & 7;
    const float* arow = g_xconv + (size_t)row * Dm;
    const float* w0 = w + (size_t)(cg * 4 + 0) * Dm;
    const float* w1 = w + (size_t)(cg * 4 + 1) * Dm;
    const float* w2 = w + (size_t)(cg * 4 + 2) * Dm;
    const float* w3 = w + (size_t)(cg * 4 + 3) * Dm;

    float a0 = 0.f, a1 = 0.f, a2 = 0.f, a3 = 0.f;
    for (int k = 0; k < Dm; k += 4) {
        float4 a = *(const float4*)(arow + k);
        float4 x0 = *(const float4*)(w0 + k);
        float4 x1 = *(const float4*)(w1 + k);
        float4 x2 = *(const float4*)(w2 + k);
        float4 x3 = *(const float4*)(w3 + k);
        a0 = fmaf(a.x, x0.x, fmaf(a.y, x0.y, fmaf(a.z, x0.z, fmaf(a.w, x0.w, a0))));
        a1 = fmaf(a.x, x1.x, fmaf(a.y, x1.y, fmaf(a.z, x1.z, fmaf(a.w, x1.w, a1))));
        a2 = fmaf(a.x, x2.x, fmaf(a.y, x2.y, fmaf(a.z, x2.z, fmaf(a.w, x2.w, a2))));
        a3 = fmaf(a.x, x3.x, fmaf(a.y, x3.y, fmaf(a.z, x3.z, fmaf(a.w, x3.w, a3))));
    }
    float* o = g_bc + (size_t)row * (2 * Ns) + cg * 4;
    o[0] = a0 + bias[cg * 4 + 0];
    o[1] = a1 + bias[cg * 4 + 1];
    o[2] = a2 + bias[cg * 4 + 2];
    o[3] = a3 + bias[cg * 4 + 3];
}

// ================= Causal depthwise conv1d (k=4) + SiLU =================
__global__ void __launch_bounds__(256)
k_conv_silu(const float* __restrict__ conv_w, const float* __restrict__ conv_b)
{
    int idx = blockIdx.x * blockDim.x + threadIdx.x;
    if (idx >= BL * Dm) return;
    int d  = idx & (Dm - 1);
    int bl = idx >> 10;
    int l  = bl & (Ll - 1);
    int b  = bl >> 11;

    float w0 = conv_w[d * 4 + 0];
    float w1 = conv_w[d * 4 + 1];
    float w2 = conv_w[d * 4 + 2];
    float w3 = conv_w[d * 4 + 3];

    const float* xp = g_xproj + (size_t)(b * Ll + l) * 2 * Dm + d;
    float acc = conv_b[d];
    acc = fmaf(w3, xp[0], acc);
    if (l >= 1) acc = fmaf(w2, xp[-2 * Dm], acc);
    if (l >= 2) acc = fmaf(w1, xp[-4 * Dm], acc);
    if (l >= 3) acc = fmaf(w0, xp[-6 * Dm], acc);

    float s = acc / (1.f + __expf(-acc));   // silu
    g_xconv[idx]   = s;
    g_xconv_h[idx] = __float2half(s);
}

// ================= Chunked selective scan =================
// Chunk length CL=256, NCHUNK=8. h is linear in its initial value:
//   over a chunk: h_end = h_start * Ptot + h_local_end
// Pass A: local scan per chunk (h from 0) -> h_local_end, Ptot.
// Pass B: compose chunk starts serially (tiny).
// Pass C: full scan per chunk with correct h_start; gate + y output.
#define SCAN_T 64
#define TPC (CL / SCAN_T)     // 4 tiles per chunk

// ---- Pass A ----
__global__ void __launch_bounds__(64)
k_scanA(const float* __restrict__ A_log)
{
    __shared__ __align__(16) float s_dt[2][SCAN_T][8];
    __shared__ __align__(16) float s_xc[2][SCAN_T][8];
    __shared__ __align__(16) float s_bc[2][SCAN_T][32];

    const int tid = threadIdx.x;
    const int nl  = tid & 7;
    const int dg  = tid >> 3;
    const int bid = blockIdx.x;
    const int c    = bid & (NCHUNK - 1);
    const int dblk = (bid >> 3) & 127;
    const int b    = bid >> 10;
    const int d = dblk * 8 + dg;
    const int r0 = b * Ll + c * CL;

    const float An0 = -__expf(A_log[d * Ns + nl]);
    const float An1 = -__expf(A_log[d * Ns + nl + 8]);

    const float* src_dt = g_dt    + (size_t)r0 * Dm + dblk * 8;
    const float* src_xc = g_xconv + (size_t)r0 * Dm + dblk * 8;
    const float* src_bc = g_bc    + (size_t)r0 * 2 * Ns;

    #define LOAD_A(t, buf)                                                                     \
    {                                                                                          \
        const int base_l = (t) * SCAN_T;                                                       \
        _Pragma("unroll")                                                                      \
        for (int ii = 0; ii < 2; ii++) {                                                       \
            const int i = tid + ii * 64;                                                       \
            const int cl = i >> 1, chf = (i & 1) * 4;                                          \
            cp16(smem_u32(&s_dt[buf][cl][chf]), src_dt + (size_t)(base_l + cl) * Dm + chf);    \
            cp16(smem_u32(&s_xc[buf][cl][chf]), src_xc + (size_t)(base_l + cl) * Dm + chf);    \
        }                                                                                      \
        _Pragma("unroll")                                                                      \
        for (int i = tid; i < SCAN_T * 8; i += 64) {                                           \
            const int bl = i >> 3, bhf = (i & 7) * 4;                                          \
            cp16(smem_u32(&s_bc[buf][bl][bhf]), src_bc + (size_t)(base_l + bl) * 32 + bhf);    \
        }                                                                                      \
        cp_commit();                                                                           \
    }

    LOAD_A(0, 0);

    float h0 = 0.f, h1 = 0.f, P0 = 1.f, P1 = 1.f;
    for (int t = 0; t < TPC; t++) {
        const int cur = t & 1;
        if (t + 1 < TPC) { LOAD_A(t + 1, cur ^ 1); cp_wait<1>(); }
        else             { cp_wait<0>(); }
        __syncthreads();

        #pragma unroll 4
        for (int l = 0; l < SCAN_T; l++) {
            float dt  = s_dt[cur][l][dg];
            float xv  = s_xc[cur][l][dg];
            float dtx = dt * xv;
            float e0 = __expf(dt * An0);
            float e1 = __expf(dt * An1);
            h0 = fmaf(h0, e0, dtx * s_bc[cur][l][nl]);
            h1 = fmaf(h1, e1, dtx * s_bc[cur][l][8 + nl]);
            P0 *= e0;
            P1 *= e1;
        }
        __syncthreads();
    }
    #undef LOAD_A

    const size_t o = ((size_t)(b * NCHUNK + c) * Dm + d) * Ns + nl;
    g_hend[o]     = h0;  g_hend[o + 8] = h1;
    g_ptot[o]     = P0;  g_ptot[o + 8] = P1;
}

// ---- Pass B: compose chunk-start states ----
__global__ void __launch_bounds__(256)
k_scanB()
{
    const int i = blockIdx.x * blockDim.x + threadIdx.x;   // over Bb*Dm*Ns
    const int n = i & 15;
    const int d = (i >> 4) & 1023;
    const int b = i >> 14;

    float hs = 0.f;
    #pragma unroll
    for (int c = 0; c < NCHUNK; c++) {
        const size_t o = ((size_t)(b * NCHUNK + c) * Dm + d) * Ns + n;
        g_hstart[o] = hs;
        hs = fmaf(hs, g_ptot[o], g_hend[o]);
    }
}

// ---- Pass C: full scan per chunk with correct start; gate + y ----
__global__ void __launch_bounds__(64)
k_scanC(const float* __restrict__ A_log, const float* __restrict__ Dvec)
{
    __shared__ __align__(16) float s_dt[2][SCAN_T][8];
    __shared__ __align__(16) float s_xc[2][SCAN_T][8];
    __shared__ __align__(16) float s_g [2][SCAN_T][8];
    __shared__ __align__(16) float s_bc[2][SCAN_T][32];
    __shared__ __align__(16) float s_p [SCAN_T][64];
    __shared__ __align__(16) float s_y [SCAN_T][8];
    __shared__ float s_D[8];

    const int tid = threadIdx.x;
    const int nl  = tid & 7;
    const int dg  = tid >> 3;
    const int bid = blockIdx.x;
    const int c    = bid & (NCHUNK - 1);
    const int dblk = (bid >> 3) & 127;
    const int b    = bid >> 10;
    const int d = dblk * 8 + dg;
    const int r0 = b * Ll + c * CL;

    const float An0 = -__expf(A_log[d * Ns + nl]);
    const float An1 = -__expf(A_log[d * Ns + nl + 8]);
    if (tid < 8) s_D[tid] = Dvec[dblk * 8 + tid];

    const float* src_dt = g_dt    + (size_t)r0 * Dm + dblk * 8;
    const float* src_xc = g_xconv + (size_t)r0 * Dm + dblk * 8;
    const float* src_g  = g_xproj + (size_t)r0 * 2 * Dm + Dm + dblk * 8;
    const float* src_bc = g_bc    + (size_t)r0 * 2 * Ns;
    __half*      p_y    = g_y_h   + (size_t)r0 * Dm + dblk * 8;

    #define LOAD_C(t, buf)                                                                     \
    {                                                                                          \
        const int base_l = (t) * SCAN_T;                                                       \
        _Pragma("unroll")                                                                      \
        for (int ii = 0; ii < 2; ii++) {                                                       \
            const int i = tid + ii * 64;                                                       \
            const int cl = i >> 1, chf = (i & 1) * 4;                                          \
            cp16(smem_u32(&s_dt[buf][cl][chf]), src_dt + (size_t)(base_l + cl) * Dm + chf);    \
            cp16(smem_u32(&s_xc[buf][cl][chf]), src_xc + (size_t)(base_l + cl) * Dm + chf);    \
            cp16(smem_u32(&s_g [buf][cl][chf]), src_g  + (size_t)(base_l + cl) * 2 * Dm + chf);\
        }                                                                                      \
        _Pragma("unroll")                                                                      \
        for (int i = tid; i < SCAN_T * 8; i += 64) {                                           \
            const int bl = i >> 3, bhf = (i & 7) * 4;                                          \
            cp16(smem_u32(&s_bc[buf][bl][bhf]), src_bc + (size_t)(base_l + bl) * 32 + bhf);    \
        }                                                                                      \
        cp_commit();                                                                           \
    }

    LOAD_C(0, 0);

    const size_t oh = ((size_t)(b * NCHUNK + c) * Dm + d) * Ns + nl;
    float h0 = g_hstart[oh];
    float h1 = g_hstart[oh + 8];

    for (int t = 0; t < TPC; t++) {
        const int cur = t & 1;
        if (t + 1 < TPC) { LOAD_C(t + 1, cur ^ 1); cp_wait<1>(); }
        else             { cp_wait<0>(); }
        __syncthreads();

        #pragma unroll 4
        for (int l = 0; l < SCAN_T; l++) {
            float dt  = s_dt[cur][l][dg];
            float xv  = s_xc[cur][l][dg];
            float dtx = dt * xv;
            h0 = fmaf(h0, __expf(dt * An0), dtx * s_bc[cur][l][nl]);
            h1 = fmaf(h1, __expf(dt * An1), dtx * s_bc[cur][l][8 + nl]);
            s_p[l][tid] = fmaf(h1, s_bc[cur][l][24 + nl], h0 * s_bc[cur][l][16 + nl]);
        }
        __syncthreads();

        // bulk partial reduce
        #pragma unroll
        for (int k = 0; k < 8; k++) {
            const int o = tid + 64 * k;
            const int l = o >> 3, dgx = o & 7;
            const float4* pp = (const float4*)&s_p[l][dgx * 8];
            float4 u = pp[0], v = pp[1];
            s_y[l][dgx] = ((u.x + u.y) + (u.z + u.w)) + ((v.x + v.y) + (v.z + v.w));
        }
        __syncthreads();

        // bulk gate + store
        {
            const int l = tid;
            const int gbase = t * SCAN_T;
            float yv[8];
            #pragma unroll
            for (int j = 0; j < 8; j++) {
                float y = s_y[l][j] + s_xc[cur][l][j] * s_D[j];
                float gg = s_g[cur][l][j];
                yv[j] = y * (gg / (1.f + __expf(-gg)));
            }
            __half2 q0 = __floats2half2_rn(yv[0], yv[1]);
            __half2 q1 = __floats2half2_rn(yv[2], yv[3]);
            __half2 q2 = __floats2half2_rn(yv[4], yv[5]);
            __half2 q3 = __floats2half2_rn(yv[6], yv[7]);
            *(uint4*)(p_y + (size_t)(gbase + l) * Dm) =
                make_uint4(*(uint32_t*)&q0, *(uint32_t*)&q1, *(uint32_t*)&q2, *(uint32_t*)&q3);
        }
        __syncthreads();
    }
    #undef LOAD_C
}

// ================= Residual + LayerNorm =================
__global__ void __launch_bounds__(256)
k_ln(const float* __restrict__ x, const float* __restrict__ gam,
     const float* __restrict__ bet, float* __restrict__ out)
{
    const int row = blockIdx.x;
    const int tid = threadIdx.x;

    float v[4];
    float s = 0.f, ss = 0.f;
    #pragma unroll
    for (int i = 0; i < 4; i++) {
        int d = tid + i * 256;
        float z = g_out[(size_t)row * Dm + d] + x[(size_t)row * Dm + d];
        v[i] = z; s += z; ss = fmaf(z, z, ss);
    }
    __shared__ float red[2][8];
    #pragma unroll
    for (int o = 16; o; o >>= 1) {
        s  += __shfl_xor_sync(0xffffffffu, s, o);
        ss += __shfl_xor_sync(0xffffffffu, ss, o);
    }
    if ((tid & 31) == 0) { red[0][tid >> 5] = s; red[1][tid >> 5] = ss; }
    __syncthreads();
    s = 0.f; ss = 0.f;
    #pragma unroll
    for (int i = 0; i < 8; i++) { s += red[0][i]; ss += red[1][i]; }

    const float mu  = s * (1.f / Dm);
    const float var = ss * (1.f / Dm) - mu * mu;
    const float rstd = rsqrtf(var + LN_EPS);

    #pragma unroll
    for (int i = 0; i < 4; i++) {
        int d = tid + i * 256;
        out[(size_t)row * Dm + d] = (v[i] - mu) * rstd * gam[d] + bet[d];
    }
}

// ================= Launch =================
extern "C" void kernel_launch(void* const* d_in, const int* in_sizes, int n_in,
                              void* d_out, int out_size)
{
    const float* x    = (const float*)d_in[0];
    const float* ipw  = (const float*)d_in[1];
    const float* ipb  = (const float*)d_in[2];
    const float* cw   = (const float*)d_in[3];
    const float* cb   = (const float*)d_in[4];
    const float* bcw  = (const float*)d_in[5];
    const float* bcb  = (const float*)d_in[6];
    const float* dtw  = (const float*)d_in[7];
    const float* dtb  = (const float*)d_in[8];
    const float* alog = (const float*)d_in[9];
    const float* Dv   = (const float*)d_in[10];
    const float* ow   = (const float*)d_in[11];
    const float* ob   = (const float*)d_in[12];
    const float* lng  = (const float*)d_in[13];
    const float* lnb  = (const float*)d_in[14];
    float* out = (float*)d_out;

    __half *xh, *ipwh, *dtwh, *owh;
    cudaGetSymbolAddress((void**)&xh,   g_xh);
    cudaGetSymbolAddress((void**)&ipwh, g_ipw_h);
    cudaGetSymbolAddress((void**)&dtwh, g_dtw_h);
    cudaGetSymbolAddress((void**)&owh,  g_ow_h);

    // 0) conversions needed before inproj (launches #0-2)
    k_f2h<<<(BL * Dm / 4 + 255) / 256, 256>>>(x, xh, BL * Dm / 4);
    k_f2h<<<(2 * Dm * Dm / 4 + 255) / 256, 256>>>(ipw, ipwh, 2 * Dm * Dm / 4);
    k_f2h<<<(Dm * Dm / 4 + 255) / 256, 256>>>(dtw, dtwh, Dm * Dm / 4);

    // 1) in_proj (fp16 mma) — launch #3 (profiled)
    k_gemm_inproj<<<dim3(2 * Dm / GBN, BL / GBM), 256>>>(ipb);

    // 2) causal depthwise conv + silu
    k_conv_silu<<<(BL * Dm) / 256, 256>>>(cw, cb);

    // 3) BC projection (thin)
    k_bc<<<BL / 32, 256>>>(bcw, bcb);

    // 4) dt projection + fused softplus (fp16 mma)
    k_gemm_dt<<<dim3(Dm / GBN, BL / GBM), 256>>>(dtb);

    // 5) chunked selective scan: A (local) -> B (compose) -> C (final + gate)
    k_scanA<<<Bb * 128 * NCHUNK, 64>>>(alog);
    k_scanB<<<(Bb * Dm * Ns) / 256, 256>>>();
    k_scanC<<<Bb * 128 * NCHUNK, 64>>>(alog, Dv);

    // 6) out-weight conversion + out projection (fp16 mma)
    k_f2h<<<(Dm * Dm / 4 + 255) / 256, 256>>>(ow, owh, Dm * Dm / 4);
    k_gemm_out<<<dim3(Dm / GBN, BL / GBM), 256>>>(ob);

    // 7) residual + layernorm
    k_ln<<<BL, 256>>>(x, lng, lnb, out);
}

// round 15
// speedup vs baseline: 1.0740x; 1.0740x over previous
#include <cuda_runtime.h>
#include <cuda_fp16.h>
#include <cstdint>

// ---------------- Problem constants ----------------
#define Bb     4
#define Ll     2048
#define Dm     1024
#define Ns     16
#define BL     (Bb * Ll)        // 8192 rows
#define LN_EPS 1e-5f

// ---------------- Scratch (device globals; no allocs allowed) ----------------
__device__ float  g_xproj[BL * 2 * Dm];   // [row][0:1024]=x_ssm, [1024:2048]=gate
__device__ float  g_xconv[BL * Dm];       // fp32 (scan, bc)
__device__ float  g_bc[BL * 2 * Ns];      // [row][0:16]=B, [16:32]=C
__device__ float  g_dt[BL * Dm];          // softplus'd
__device__ float  g_out[BL * Dm];         // after out proj, before LN
// fp16 operands for tensor-core GEMMs
__device__ __half g_xh[BL * Dm];
__device__ __half g_xconv_h[BL * Dm];
__device__ __half g_y_h[BL * Dm];
__device__ __half g_ipw_h[2 * Dm * Dm];
__device__ __half g_dtw_h[Dm * Dm];
__device__ __half g_ow_h[Dm * Dm];

__device__ __forceinline__ float softplus_f(float v) {
    return (v > 20.f) ? v : log1pf(__expf(v));
}

__device__ __forceinline__ uint32_t smem_u32(const void* p) {
    return (uint32_t)__cvta_generic_to_shared(p);
}
__device__ __forceinline__ void cp16(uint32_t dst, const void* src) {
    asm volatile("cp.async.cg.shared.global [%0], [%1], 16;\n" :: "r"(dst), "l"(src));
}
__device__ __forceinline__ void cp_commit() { asm volatile("cp.async.commit_group;\n"); }
template<int W> __device__ __forceinline__ void cp_wait() {
    asm volatile("cp.async.wait_group %0;\n" :: "n"(W));
}

// ================= f32 -> f16 conversion =================
__global__ void __launch_bounds__(256)
k_f2h(const float* __restrict__ src, __half* __restrict__ dst, int n4)
{
    int i = blockIdx.x * blockDim.x + threadIdx.x;
    if (i >= n4) return;
    float4 v = *(const float4*)(src + (size_t)i * 4);
    __half2 h0 = __floats2half2_rn(v.x, v.y);
    __half2 h1 = __floats2half2_rn(v.z, v.w);
    *(uint2*)(dst + (size_t)i * 4) = make_uint2(*(uint32_t*)&h0, *(uint32_t*)&h1);
}

// ================= fp16 tensor-core GEMM (proven 2-stage version) =================
#define GBM 128
#define GBN 128
#define GBK 32
#define LDAH 40   // halves per smem row (32 + 8 pad) -> conflict-free frag loads

__device__ __forceinline__ void mma_f16(float& c0, float& c1, float& c2, float& c3,
                                        uint32_t a0, uint32_t a1, uint32_t a2, uint32_t a3,
                                        uint32_t b0, uint32_t b1) {
    asm volatile(
        "mma.sync.aligned.m16n8k16.row.col.f32.f16.f16.f32 "
        "{%0,%1,%2,%3},{%4,%5,%6,%7},{%8,%9},{%0,%1,%2,%3};\n"
        : "+f"(c0), "+f"(c1), "+f"(c2), "+f"(c3)
        : "r"(a0), "r"(a1), "r"(a2), "r"(a3), "r"(b0), "r"(b1));
}

template<int ACT>
__device__ __forceinline__ void gemm_f16_body(const __half* __restrict__ A,
                                              const __half* __restrict__ Bw,
                                              const float* __restrict__ bias,
                                              float* __restrict__ C,
                                              int N, int K)
{
    __shared__ __align__(16) __half As[2][GBM][LDAH];
    __shared__ __align__(16) __half Bs[2][GBN][LDAH];

    const int tid  = threadIdx.x;
    const int lane = tid & 31;
    const int wid  = tid >> 5;
    const int g    = lane >> 2;
    const int tig  = lane & 3;
    const int warpM = wid >> 2;
    const int warpN = wid & 3;
    const int bm = blockIdx.y * GBM;
    const int bn = blockIdx.x * GBN;

    float c[4][4][4];
    #pragma unroll
    for (int mt = 0; mt < 4; mt++)
        #pragma unroll
        for (int nt = 0; nt < 4; nt++)
            #pragma unroll
            for (int r = 0; r < 4; r++) c[mt][nt][r] = 0.f;

    const int i0 = 2 * tid, i1 = 2 * tid + 1;
    const int r0c = i0 >> 2, o0 = (i0 & 3) * 8;
    const int r1c = i1 >> 2, o1 = (i1 & 3) * 8;
    const __half* Arow0 = A  + (size_t)(bm + r0c) * K + o0;
    const __half* Arow1 = A  + (size_t)(bm + r1c) * K + o1;
    const __half* Brow0 = Bw + (size_t)(bn + r0c) * K + o0;
    const __half* Brow1 = Bw + (size_t)(bn + r1c) * K + o1;
    uint32_t dA0 = smem_u32(&As[0][r0c][o0]);
    uint32_t dA1 = smem_u32(&As[0][r1c][o1]);
    uint32_t dB0 = smem_u32(&Bs[0][r0c][o0]);
    uint32_t dB1 = smem_u32(&Bs[0][r1c][o1]);
    const uint32_t bufStride = (uint32_t)(GBM * LDAH * 2);

    cp16(dA0, Arow0); cp16(dA1, Arow1);
    cp16(dB0, Brow0); cp16(dB1, Brow1);
    cp_commit();

    const int NK = K / GBK;
    for (int it = 0; it < NK; it++) {
        const int cur = it & 1;
        cp_wait<0>();
        __syncthreads();
        if (it + 1 < NK) {
            const int nxt = cur ^ 1;
            const int k0 = (it + 1) * GBK;
            cp16(dA0 + nxt * bufStride, Arow0 + k0);
            cp16(dA1 + nxt * bufStride, Arow1 + k0);
            cp16(dB0 + nxt * bufStride, Brow0 + k0);
            cp16(dB1 + nxt * bufStride, Brow1 + k0);
            cp_commit();
        }

        #pragma unroll
        for (int ks = 0; ks < 2; ks++) {
            const int kk = ks * 16;
            uint32_t a[4][4], bf[4][2];
            #pragma unroll
            for (int mt = 0; mt < 4; mt++) {
                const int m0 = warpM * 64 + mt * 16 + g;
                a[mt][0] = *(const uint32_t*)&As[cur][m0    ][kk + 2 * tig    ];
                a[mt][1] = *(const uint32_t*)&As[cur][m0 + 8][kk + 2 * tig    ];
                a[mt][2] = *(const uint32_t*)&As[cur][m0    ][kk + 2 * tig + 8];
                a[mt][3] = *(const uint32_t*)&As[cur][m0 + 8][kk + 2 * tig + 8];
            }
            #pragma unroll
            for (int nt = 0; nt < 4; nt++) {
                const int n0 = warpN * 32 + nt * 8 + g;
                bf[nt][0] = *(const uint32_t*)&Bs[cur][n0][kk + 2 * tig    ];
                bf[nt][1] = *(const uint32_t*)&Bs[cur][n0][kk + 2 * tig + 8];
            }
            #pragma unroll
            for (int mt = 0; mt < 4; mt++)
                #pragma unroll
                for (int nt = 0; nt < 4; nt++)
                    mma_f16(c[mt][nt][0], c[mt][nt][1], c[mt][nt][2], c[mt][nt][3],
                            a[mt][0], a[mt][1], a[mt][2], a[mt][3],
                            bf[nt][0], bf[nt][1]);
        }
    }

    #pragma unroll
    for (int mt = 0; mt < 4; mt++) {
        const int m = bm + warpM * 64 + mt * 16 + g;
        #pragma unroll
        for (int nt = 0; nt < 4; nt++) {
            const int n = bn + warpN * 32 + nt * 8 + tig * 2;
            const float b0v = bias[n], b1v = bias[n + 1];
            float v0 = c[mt][nt][0] + b0v;
            float v1 = c[mt][nt][1] + b1v;
            float v2 = c[mt][nt][2] + b0v;
            float v3 = c[mt][nt][3] + b1v;
            if (ACT == 1) { v0 = softplus_f(v0); v1 = softplus_f(v1); v2 = softplus_f(v2); v3 = softplus_f(v3); }
            *(float2*)&C[(size_t)m * N + n]       = make_float2(v0, v1);
            *(float2*)&C[(size_t)(m + 8) * N + n] = make_float2(v2, v3);
        }
    }
}

__global__ void __launch_bounds__(256)
k_gemm_inproj(const float* __restrict__ b)
{ gemm_f16_body<0>(g_xh, g_ipw_h, b, g_xproj, 2 * Dm, Dm); }

__global__ void __launch_bounds__(256)
k_gemm_dt(const float* __restrict__ b)
{ gemm_f16_body<1>(g_xconv_h, g_dtw_h, b, g_dt, Dm, Dm); }

__global__ void __launch_bounds__(256)
k_gemm_out(const float* __restrict__ b)
{ gemm_f16_body<0>(g_y_h, g_ow_h, b, g_out, Dm, Dm); }

// ================= thin BC projection: (8192,1024) @ (32,1024)^T =================
__global__ void __launch_bounds__(256)
k_bc(const float* __restrict__ w, const float* __restrict__ bias)
{
    const int row = blockIdx.x * 32 + (threadIdx.x >> 3);
    const int cg  = threadIdx.x & 7;
    const float* arow = g_xconv + (size_t)row * Dm;
    const float* w0 = w + (size_t)(cg * 4 + 0) * Dm;
    const float* w1 = w + (size_t)(cg * 4 + 1) * Dm;
    const float* w2 = w + (size_t)(cg * 4 + 2) * Dm;
    const float* w3 = w + (size_t)(cg * 4 + 3) * Dm;

    float a0 = 0.f, a1 = 0.f, a2 = 0.f, a3 = 0.f;
    for (int k = 0; k < Dm; k += 4) {
        float4 a = *(const float4*)(arow + k);
        float4 x0 = *(const float4*)(w0 + k);
        float4 x1 = *(const float4*)(w1 + k);
        float4 x2 = *(const float4*)(w2 + k);
        float4 x3 = *(const float4*)(w3 + k);
        a0 = fmaf(a.x, x0.x, fmaf(a.y, x0.y, fmaf(a.z, x0.z, fmaf(a.w, x0.w, a0))));
        a1 = fmaf(a.x, x1.x, fmaf(a.y, x1.y, fmaf(a.z, x1.z, fmaf(a.w, x1.w, a1))));
        a2 = fmaf(a.x, x2.x, fmaf(a.y, x2.y, fmaf(a.z, x2.z, fmaf(a.w, x2.w, a2))));
        a3 = fmaf(a.x, x3.x, fmaf(a.y, x3.y, fmaf(a.z, x3.z, fmaf(a.w, x3.w, a3))));
    }
    float* o = g_bc + (size_t)row * (2 * Ns) + cg * 4;
    o[0] = a0 + bias[cg * 4 + 0];
    o[1] = a1 + bias[cg * 4 + 1];
    o[2] = a2 + bias[cg * 4 + 2];
    o[3] = a3 + bias[cg * 4 + 3];
}

// ================= Causal depthwise conv1d (k=4) + SiLU =================
__global__ void __launch_bounds__(256)
k_conv_silu(const float* __restrict__ conv_w, const float* __restrict__ conv_b)
{
    int idx = blockIdx.x * blockDim.x + threadIdx.x;
    if (idx >= BL * Dm) return;
    int d  = idx & (Dm - 1);
    int bl = idx >> 10;
    int l  = bl & (Ll - 1);
    int b  = bl >> 11;

    float w0 = conv_w[d * 4 + 0];
    float w1 = conv_w[d * 4 + 1];
    float w2 = conv_w[d * 4 + 2];
    float w3 = conv_w[d * 4 + 3];

    const float* xp = g_xproj + (size_t)(b * Ll + l) * 2 * Dm + d;
    float acc = conv_b[d];
    acc = fmaf(w3, xp[0], acc);
    if (l >= 1) acc = fmaf(w2, xp[-2 * Dm], acc);
    if (l >= 2) acc = fmaf(w1, xp[-4 * Dm], acc);
    if (l >= 3) acc = fmaf(w0, xp[-6 * Dm], acc);

    float s = acc / (1.f + __expf(-acc));   // silu
    g_xconv[idx]   = s;
    g_xconv_h[idx] = __float2half(s);
}

// ================= Selective scan (r12 design + merged reduce/gate pass) =================
// Block = 64 threads = 8 d x 8 lanes, 2 states/thread. Serial loop stores scalar
// products to padded s_p; one bulk pass reduces + gates + stores per timestep row.
#define SCAN_T 64
#define SCAN_NT (Ll / SCAN_T)     // 32
#define PLD 68                    // s_p row stride (64 + 4 pad)

__global__ void __launch_bounds__(64)
k_scan(const float* __restrict__ A_log, const float* __restrict__ Dvec)
{
    __shared__ __align__(16) float s_dt[2][SCAN_T][8];
    __shared__ __align__(16) float s_xc[2][SCAN_T][8];
    __shared__ __align__(16) float s_g [2][SCAN_T][8];
    __shared__ __align__(16) float s_bc[2][SCAN_T][32];
    __shared__ __align__(16) float s_p [SCAN_T][PLD];
    __shared__ float s_D[8];

    const int tid = threadIdx.x;
    const int nl  = tid & 7;
    const int dg  = tid >> 3;
    const int b    = blockIdx.x >> 7;
    const int dblk = blockIdx.x & 127;
    const int d = dblk * 8 + dg;
    const int r0 = b * Ll;

    const float An0 = -__expf(A_log[d * Ns + nl]);
    const float An1 = -__expf(A_log[d * Ns + nl + 8]);
    if (tid < 8) s_D[tid] = Dvec[dblk * 8 + tid];

    const float* src_dt = g_dt    + (size_t)r0 * Dm + dblk * 8;
    const float* src_xc = g_xconv + (size_t)r0 * Dm + dblk * 8;
    const float* src_g  = g_xproj + (size_t)r0 * 2 * Dm + Dm + dblk * 8;
    const float* src_bc = g_bc    + (size_t)r0 * 2 * Ns;
    __half*      p_y    = g_y_h   + (size_t)r0 * Dm + dblk * 8;

    #define LOAD_TILE(t, buf)                                                                  \
    {                                                                                          \
        const int base_l = (t) * SCAN_T;                                                       \
        _Pragma("unroll")                                                                      \
        for (int ii = 0; ii < 2; ii++) {                                                       \
            const int i = tid + ii * 64;                                                       \
            const int cl = i >> 1, chf = (i & 1) * 4;                                          \
            cp16(smem_u32(&s_dt[buf][cl][chf]), src_dt + (size_t)(base_l + cl) * Dm + chf);    \
            cp16(smem_u32(&s_xc[buf][cl][chf]), src_xc + (size_t)(base_l + cl) * Dm + chf);    \
            cp16(smem_u32(&s_g [buf][cl][chf]), src_g  + (size_t)(base_l + cl) * 2 * Dm + chf);\
        }                                                                                      \
        _Pragma("unroll")                                                                      \
        for (int i = tid; i < SCAN_T * 8; i += 64) {                                           \
            const int bl = i >> 3, bhf = (i & 7) * 4;                                          \
            cp16(smem_u32(&s_bc[buf][bl][bhf]), src_bc + (size_t)(base_l + bl) * 32 + bhf);    \
        }                                                                                      \
        cp_commit();                                                                           \
    }

    LOAD_TILE(0, 0);

    float h0 = 0.f, h1 = 0.f;
    for (int t = 0; t < SCAN_NT; t++) {
        const int cur = t & 1;
        if (t + 1 < SCAN_NT) {
            LOAD_TILE(t + 1, cur ^ 1);
            cp_wait<1>();
        } else {
            cp_wait<0>();
        }
        __syncthreads();

        // serial recurrence: no shfl, critical path = one FMA on h
        #pragma unroll 4
        for (int l = 0; l < SCAN_T; l++) {
            float dt  = s_dt[cur][l][dg];
            float xv  = s_xc[cur][l][dg];
            float dtx = dt * xv;
            h0 = fmaf(h0, __expf(dt * An0), dtx * s_bc[cur][l][nl]);
            h1 = fmaf(h1, __expf(dt * An1), dtx * s_bc[cur][l][8 + nl]);
            s_p[l][tid] = fmaf(h1, s_bc[cur][l][24 + nl], h0 * s_bc[cur][l][16 + nl]);
        }
        __syncthreads();

        // merged reduce + gate + store: thread t owns timestep row l = t
        {
            const int l = tid;
            const int gbase = t * SCAN_T;
            float yv[8];
            #pragma unroll
            for (int j = 0; j < 8; j++) {
                const float4* pp = (const float4*)&s_p[l][j * 8];
                float4 u = pp[0], v = pp[1];
                float red = ((u.x + u.y) + (u.z + u.w)) + ((v.x + v.y) + (v.z + v.w));
                float y = red + s_xc[cur][l][j] * s_D[j];
                float gg = s_g[cur][l][j];
                yv[j] = y * (gg / (1.f + __expf(-gg)));
            }
            __half2 q0 = __floats2half2_rn(yv[0], yv[1]);
            __half2 q1 = __floats2half2_rn(yv[2], yv[3]);
            __half2 q2 = __floats2half2_rn(yv[4], yv[5]);
            __half2 q3 = __floats2half2_rn(yv[6], yv[7]);
            *(uint4*)(p_y + (size_t)(gbase + l) * Dm) =
                make_uint4(*(uint32_t*)&q0, *(uint32_t*)&q1, *(uint32_t*)&q2, *(uint32_t*)&q3);
        }
        __syncthreads();
    }
    #undef LOAD_TILE
}

// ================= Residual + LayerNorm =================
__global__ void __launch_bounds__(256)
k_ln(const float* __restrict__ x, const float* __restrict__ gam,
     const float* __restrict__ bet, float* __restrict__ out)
{
    const int row = blockIdx.x;
    const int tid = threadIdx.x;

    float v[4];
    float s = 0.f, ss = 0.f;
    #pragma unroll
    for (int i = 0; i < 4; i++) {
        int d = tid + i * 256;
        float z = g_out[(size_t)row * Dm + d] + x[(size_t)row * Dm + d];
        v[i] = z; s += z; ss = fmaf(z, z, ss);
    }
    __shared__ float red[2][8];
    #pragma unroll
    for (int o = 16; o; o >>= 1) {
        s  += __shfl_xor_sync(0xffffffffu, s, o);
        ss += __shfl_xor_sync(0xffffffffu, ss, o);
    }
    if ((tid & 31) == 0) { red[0][tid >> 5] = s; red[1][tid >> 5] = ss; }
    __syncthreads();
    s = 0.f; ss = 0.f;
    #pragma unroll
    for (int i = 0; i < 8; i++) { s += red[0][i]; ss += red[1][i]; }

    const float mu  = s * (1.f / Dm);
    const float var = ss * (1.f / Dm) - mu * mu;
    const float rstd = rsqrtf(var + LN_EPS);

    #pragma unroll
    for (int i = 0; i < 4; i++) {
        int d = tid + i * 256;
        out[(size_t)row * Dm + d] = (v[i] - mu) * rstd * gam[d] + bet[d];
    }
}

// ================= Launch =================
extern "C" void kernel_launch(void* const* d_in, const int* in_sizes, int n_in,
                              void* d_out, int out_size)
{
    const float* x    = (const float*)d_in[0];
    const float* ipw  = (const float*)d_in[1];
    const float* ipb  = (const float*)d_in[2];
    const float* cw   = (const float*)d_in[3];
    const float* cb   = (const float*)d_in[4];
    const float* bcw  = (const float*)d_in[5];
    const float* bcb  = (const float*)d_in[6];
    const float* dtw  = (const float*)d_in[7];
    const float* dtb  = (const float*)d_in[8];
    const float* alog = (const float*)d_in[9];
    const float* Dv   = (const float*)d_in[10];
    const float* ow   = (const float*)d_in[11];
    const float* ob   = (const float*)d_in[12];
    const float* lng  = (const float*)d_in[13];
    const float* lnb  = (const float*)d_in[14];
    float* out = (float*)d_out;

    __half *xh, *ipwh, *dtwh, *owh;
    cudaGetSymbolAddress((void**)&xh,   g_xh);
    cudaGetSymbolAddress((void**)&ipwh, g_ipw_h);
    cudaGetSymbolAddress((void**)&dtwh, g_dtw_h);
    cudaGetSymbolAddress((void**)&owh,  g_ow_h);

    // launch order arranged so k_conv_silu is launch #4 (ncu capture slot)
    // 1) x conversion
    k_f2h<<<(BL * Dm / 4 + 255) / 256, 256>>>(x, xh, BL * Dm / 4);
    // 2) inproj weight conversion
    k_f2h<<<(2 * Dm * Dm / 4 + 255) / 256, 256>>>(ipw, ipwh, 2 * Dm * Dm / 4);
    // 3) in_proj (fp16 mma)
    k_gemm_inproj<<<dim3(2 * Dm / GBN, BL / GBM), 256>>>(ipb);
    // 4) causal depthwise conv + silu  <-- profiled this round
    k_conv_silu<<<(BL * Dm) / 256, 256>>>(cw, cb);
    // 5) dt weight conversion
    k_f2h<<<(Dm * Dm / 4 + 255) / 256, 256>>>(dtw, dtwh, Dm * Dm / 4);
    // 6) BC projection (thin)
    k_bc<<<BL / 32, 256>>>(bcw, bcb);
    // 7) dt projection + fused softplus (fp16 mma)
    k_gemm_dt<<<dim3(Dm / GBN, BL / GBM), 256>>>(dtb);
    // 8) selective scan + gate (merged bulk pass)
    k_scan<<<Bb * (Dm / 8), 64>>>(alog, Dv);
    // 9) out weight conversion
    k_f2h<<<(Dm * Dm / 4 + 255) / 256, 256>>>(ow, owh, Dm * Dm / 4);
    // 10) out projection (fp16 mma)
    k_gemm_out<<<dim3(Dm / GBN, BL / GBM), 256>>>(ob);
    // 11) residual + layernorm
    k_ln<<<BL, 256>>>(x, lng, lnb, out);
}